// round 2
// baseline (speedup 1.0000x reference)
#include <cuda_runtime.h>
#include <cuda_bf16.h>

// Problem: B=32, N=128, D=512, A=512
//   x1 = x @ W1^T + b1   (B*N, A)
//   x2 = x @ W2^T + b2
//   out[b,i,j] = sum_a Wout[a]*tanh(x1[b,j,a] + x2[b,i+1,a]) + bout[0]
//   out shape (32, 127, 128) fp32

#define Bq 32
#define Nq 128
#define Dq 512
#define Aq 512
#define Mq (Bq*Nq)   // 4096

__device__ float g_x1[Mq*Aq];
__device__ float g_x2[Mq*Aq];

__device__ __forceinline__ float tanh_fast(float x) {
    float y;
    asm("tanh.approx.f32 %0, %1;" : "=f"(y) : "f"(x));
    return y;
}

// ---------------- GEMM (NT, fp32 SIMT): dst[m,a] = sum_d X[m,d]*W[a,d] + bias[a]
// BM=BN=64, BK=16, 256 threads, 4x4 microtile.
__global__ __launch_bounds__(256) void gemm_nt(const float* __restrict__ X,
                                               const float* __restrict__ W,
                                               const float* __restrict__ bias,
                                               int which) {
    __shared__ float xs[16][68];
    __shared__ float ws[16][68];
    float* dst = which ? g_x2 : g_x1;

    const int bm = blockIdx.y * 64;
    const int bn = blockIdx.x * 64;
    const int tid = threadIdx.x;
    const int lr = tid >> 2;          // 0..63
    const int lc = (tid & 3) << 2;    // 0,4,8,12
    const int ty = tid >> 4;          // 0..15  -> rows
    const int tx = tid & 15;          // 0..15  -> cols

    float acc[4][4];
#pragma unroll
    for (int i = 0; i < 4; i++)
#pragma unroll
        for (int j = 0; j < 4; j++) acc[i][j] = 0.f;

    const float* xp = X + (bm + lr) * Dq + lc;
    const float* wp = W + (bn + lr) * Dq + lc;

    for (int k0 = 0; k0 < Dq; k0 += 16) {
        float4 xv = *(const float4*)(xp + k0);
        float4 wv = *(const float4*)(wp + k0);
        __syncthreads();
        xs[lc + 0][lr] = xv.x; xs[lc + 1][lr] = xv.y;
        xs[lc + 2][lr] = xv.z; xs[lc + 3][lr] = xv.w;
        ws[lc + 0][lr] = wv.x; ws[lc + 1][lr] = wv.y;
        ws[lc + 2][lr] = wv.z; ws[lc + 3][lr] = wv.w;
        __syncthreads();
#pragma unroll
        for (int kk = 0; kk < 16; kk++) {
            float4 av = *(const float4*)&xs[kk][ty << 2];
            float4 bv = *(const float4*)&ws[kk][tx << 2];
            acc[0][0] += av.x * bv.x; acc[0][1] += av.x * bv.y;
            acc[0][2] += av.x * bv.z; acc[0][3] += av.x * bv.w;
            acc[1][0] += av.y * bv.x; acc[1][1] += av.y * bv.y;
            acc[1][2] += av.y * bv.z; acc[1][3] += av.y * bv.w;
            acc[2][0] += av.z * bv.x; acc[2][1] += av.z * bv.y;
            acc[2][2] += av.z * bv.z; acc[2][3] += av.z * bv.w;
            acc[3][0] += av.w * bv.x; acc[3][1] += av.w * bv.y;
            acc[3][2] += av.w * bv.z; acc[3][3] += av.w * bv.w;
        }
    }

#pragma unroll
    for (int i = 0; i < 4; i++) {
        int m = bm + (ty << 2) + i;
#pragma unroll
        for (int j = 0; j < 4; j++) {
            int n = bn + (tx << 2) + j;
            dst[m * Aq + n] = acc[i][j] + bias[n];
        }
    }
}

// ---------------- tanh + weighted reduction
// Block: one b, 32 i's x 32 j's. 256 threads, each owns a 2x2 (i,j) microtile,
// full reduction over a=512 in registers. smem rows padded to stride 516.
#define ROWS 32
#define RSTRIDE 516
#define SMEM_TANH ((2 * ROWS * RSTRIDE + Aq) * 4)

__global__ __launch_bounds__(256) void tanh_reduce(const float* __restrict__ Wout,
                                                   const float* __restrict__ bout,
                                                   float* __restrict__ out) {
    extern __shared__ float sm[];
    float* s1 = sm;                       // [32][516] x1 rows (j)
    float* s2 = sm + ROWS * RSTRIDE;      // [32][516] x2 rows (i+1)
    float* sw = sm + 2 * ROWS * RSTRIDE;  // [512]

    const int b  = blockIdx.z;
    const int it = blockIdx.y;
    const int jt = blockIdx.x;
    const int tid = threadIdx.x;
    const int j0base = jt * ROWS;
    const int i0base = it * ROWS;

    const float* x1b = g_x1 + (size_t)b * Nq * Aq;
    const float* x2b = g_x2 + (size_t)b * Nq * Aq;

    // Load 32 rows of x1 (j) and x2 (i+1), 4096 float4 each.
    for (int idx = tid; idx < ROWS * (Aq / 4); idx += 256) {
        int row = idx >> 7;      // / (512/4)
        int c4  = idx & 127;
        *(float4*)(s1 + row * RSTRIDE + c4 * 4) =
            *(const float4*)(x1b + (j0base + row) * Aq + c4 * 4);
        int ii = i0base + row;
        float4 v = make_float4(0.f, 0.f, 0.f, 0.f);
        if (ii < Nq - 1) v = *(const float4*)(x2b + (ii + 1) * Aq + c4 * 4);
        *(float4*)(s2 + row * RSTRIDE + c4 * 4) = v;
    }
    if (tid < Aq / 4) *(float4*)(sw + tid * 4) = ((const float4*)Wout)[tid];
    __syncthreads();

    const int ti = tid >> 4;   // 0..15
    const int tj = tid & 15;   // 0..15

    const float* r1a = s1 + tj * RSTRIDE;
    const float* r1b = s1 + (tj + 16) * RSTRIDE;
    const float* r2a = s2 + ti * RSTRIDE;
    const float* r2b = s2 + (ti + 16) * RSTRIDE;

    float acc00 = 0.f, acc01 = 0.f, acc10 = 0.f, acc11 = 0.f;

#pragma unroll 2
    for (int a4 = 0; a4 < Aq / 4; a4++) {
        float4 w = *(const float4*)(sw + a4 * 4);
        float4 p = *(const float4*)(r1a + a4 * 4);   // x1[j0]
        float4 q = *(const float4*)(r1b + a4 * 4);   // x1[j1]
        float4 u = *(const float4*)(r2a + a4 * 4);   // x2[i0+1]
        float4 v = *(const float4*)(r2b + a4 * 4);   // x2[i1+1]

        acc00 += w.x * tanh_fast(u.x + p.x);
        acc00 += w.y * tanh_fast(u.y + p.y);
        acc00 += w.z * tanh_fast(u.z + p.z);
        acc00 += w.w * tanh_fast(u.w + p.w);

        acc01 += w.x * tanh_fast(u.x + q.x);
        acc01 += w.y * tanh_fast(u.y + q.y);
        acc01 += w.z * tanh_fast(u.z + q.z);
        acc01 += w.w * tanh_fast(u.w + q.w);

        acc10 += w.x * tanh_fast(v.x + p.x);
        acc10 += w.y * tanh_fast(v.y + p.y);
        acc10 += w.z * tanh_fast(v.z + p.z);
        acc10 += w.w * tanh_fast(v.w + p.w);

        acc11 += w.x * tanh_fast(v.x + q.x);
        acc11 += w.y * tanh_fast(v.y + q.y);
        acc11 += w.z * tanh_fast(v.z + q.z);
        acc11 += w.w * tanh_fast(v.w + q.w);
    }

    const float bo = bout[0];
    const int i0g = i0base + ti, i1g = i0g + 16;
    const int j0g = j0base + tj, j1g = j0g + 16;
    float* ob = out + (size_t)b * (Nq - 1) * Nq;

    if (i0g < Nq - 1) {
        ob[i0g * Nq + j0g] = acc00 + bo;
        ob[i0g * Nq + j1g] = acc01 + bo;
    }
    if (i1g < Nq - 1) {
        ob[i1g * Nq + j0g] = acc10 + bo;
        ob[i1g * Nq + j1g] = acc11 + bo;
    }
}

extern "C" void kernel_launch(void* const* d_in, const int* in_sizes, int n_in,
                              void* d_out, int out_size) {
    const float* x    = (const float*)d_in[0];
    const float* W1   = (const float*)d_in[1];
    const float* b1   = (const float*)d_in[2];
    const float* W2   = (const float*)d_in[3];
    const float* b2   = (const float*)d_in[4];
    const float* Wout = (const float*)d_in[5];
    const float* bout = (const float*)d_in[6];
    float* out = (float*)d_out;

    cudaFuncSetAttribute(tanh_reduce, cudaFuncAttributeMaxDynamicSharedMemorySize,
                         SMEM_TANH);

    dim3 ggrid(Aq / 64, Mq / 64);      // (8, 64)
    gemm_nt<<<ggrid, 256>>>(x, W1, b1, 0);
    gemm_nt<<<ggrid, 256>>>(x, W2, b2, 1);

    dim3 tgrid(Nq / ROWS, Nq / ROWS, Bq);  // (4, 4, 32)
    tanh_reduce<<<tgrid, 256, SMEM_TANH>>>(Wout, bout, out);
}

// round 5
// speedup vs baseline: 1.4333x; 1.4333x over previous
#include <cuda_runtime.h>
#include <cuda_bf16.h>
#include <cstdint>

// Problem: B=32, N=128, D=512, A=512
//   x1 = x @ W1^T + b1   (B*N, A)
//   x2 = x @ W2^T + b2
//   out[b,i,j] = sum_a Wout[a]*tanh(x1[b,j,a] + x2[b,i+1,a]) + bout[0]
// GEMM via bf16 3-split tensor cores: A' = [hi|lo|hi] (K=1536), B' = [hi|hi|lo].

#define Bq 32
#define Nq 128
#define Dq 512
#define Aq 512
#define Mq (Bq*Nq)     // 4096
#define KK 1536        // 3*512 split-K
#define NN 1024        // two weight matrices stacked

__device__ float g_x1[Mq*Aq];
__device__ float g_x2[Mq*Aq];
__device__ __nv_bfloat16 g_A[(size_t)Mq*KK];   // x split   [4096][1536]
__device__ __nv_bfloat16 g_B[(size_t)NN*KK];   // W split   [1024][1536]
__device__ float g_bias[NN];

__device__ __forceinline__ float tanh_fast(float x) {
    float y;
    asm("tanh.approx.f32 %0, %1;" : "=f"(y) : "f"(x));
    return y;
}

__device__ __forceinline__ uint32_t pack_bf2(__nv_bfloat16 a, __nv_bfloat16 b) {
    return (uint32_t)__bfloat16_as_ushort(a) | ((uint32_t)__bfloat16_as_ushort(b) << 16);
}

// ---------------- split kernels (fp32 -> bf16 hi/lo, 3-way K layout)
__global__ __launch_bounds__(256) void split_x(const float* __restrict__ x) {
    int idx = blockIdx.x * 256 + threadIdx.x;
    if (idx >= Mq * (Dq / 4)) return;
    int m = idx >> 7;          // / 128
    int k4 = idx & 127;
    float4 v = ((const float4*)x)[idx];
    float vv[4] = {v.x, v.y, v.z, v.w};
    __nv_bfloat16 h[4], l[4];
#pragma unroll
    for (int i = 0; i < 4; i++) {
        h[i] = __float2bfloat16(vv[i]);
        l[i] = __float2bfloat16(vv[i] - __bfloat162float(h[i]));
    }
    uint2 hu, lu;
    hu.x = pack_bf2(h[0], h[1]); hu.y = pack_bf2(h[2], h[3]);
    lu.x = pack_bf2(l[0], l[1]); lu.y = pack_bf2(l[2], l[3]);
    __nv_bfloat16* dst = g_A + (size_t)m * KK + k4 * 4;
    *(uint2*)(dst)        = hu;   // k [0,512)    : hi
    *(uint2*)(dst + 512)  = lu;   // k [512,1024) : lo
    *(uint2*)(dst + 1024) = hu;   // k [1024,1536): hi
}

__global__ __launch_bounds__(256) void split_w(const float* __restrict__ W1,
                                               const float* __restrict__ W2,
                                               const float* __restrict__ b1,
                                               const float* __restrict__ b2) {
    int idx = blockIdx.x * 256 + threadIdx.x;
    if (idx < NN) g_bias[idx] = (idx < Aq) ? b1[idx] : b2[idx - Aq];
    if (idx >= NN * (Dq / 4)) return;
    int n = idx >> 7;
    int k4 = idx & 127;
    const float* src = (n < Aq) ? (W1 + (size_t)n * Dq) : (W2 + (size_t)(n - Aq) * Dq);
    float4 v = ((const float4*)src)[k4];
    float vv[4] = {v.x, v.y, v.z, v.w};
    __nv_bfloat16 h[4], l[4];
#pragma unroll
    for (int i = 0; i < 4; i++) {
        h[i] = __float2bfloat16(vv[i]);
        l[i] = __float2bfloat16(vv[i] - __bfloat162float(h[i]));
    }
    uint2 hu, lu;
    hu.x = pack_bf2(h[0], h[1]); hu.y = pack_bf2(h[2], h[3]);
    lu.x = pack_bf2(l[0], l[1]); lu.y = pack_bf2(l[2], l[3]);
    __nv_bfloat16* dst = g_B + (size_t)n * KK + k4 * 4;
    *(uint2*)(dst)        = hu;   // hi
    *(uint2*)(dst + 512)  = hu;   // hi (pairs with A lo)
    *(uint2*)(dst + 1024) = lu;   // lo (pairs with A hi)
}

// ---------------- bf16 tensor-core GEMM: C[m,n] = sum_k A'[m,k]*B'[n,k] + bias[n]
// BM=128, BN=128, BK=64, 256 threads = 8 warps (2 along M x 4 along N),
// warp tile 64x32, mma.sync m16n8k16, cp.async 2-stage pipeline.
#define BM 128
#define BN 128
#define BKg 64
#define LDSS 72                    // padded smem row stride (bf16 elems)
#define STAGE ((BM + BN) * LDSS)   // elems per stage
#define SMEMG (2 * STAGE * 2)      // bytes (2 stages)

#define LDSM_X4(r, addr) \
    asm volatile("ldmatrix.sync.aligned.m8n8.x4.shared.b16 {%0,%1,%2,%3}, [%4];" \
                 : "=r"((r)[0]), "=r"((r)[1]), "=r"((r)[2]), "=r"((r)[3]) : "r"(addr))

#define MMA_BF16(d, a, b0, b1) \
    asm volatile("mma.sync.aligned.m16n8k16.row.col.f32.bf16.bf16.f32 " \
                 "{%0,%1,%2,%3}, {%4,%5,%6,%7}, {%8,%9}, {%0,%1,%2,%3};" \
                 : "+f"((d)[0]), "+f"((d)[1]), "+f"((d)[2]), "+f"((d)[3]) \
                 : "r"((a)[0]), "r"((a)[1]), "r"((a)[2]), "r"((a)[3]), "r"(b0), "r"(b1))

__global__ __launch_bounds__(256, 2) void gemm_bf16() {
    extern __shared__ __nv_bfloat16 sm[];
    const int tid = threadIdx.x;
    const int warp = tid >> 5, lane = tid & 31;
    const int wm = warp & 1;        // 0..1 -> 64-row slab
    const int wn = warp >> 1;       // 0..3 -> 32-col slab
    const int bm = blockIdx.y * BM;
    const int bn = blockIdx.x * BN;

    float acc[4][4][4];             // [mi 16-row][ng 8-col][frag]
#pragma unroll
    for (int i = 0; i < 4; i++)
#pragma unroll
        for (int j = 0; j < 4; j++)
#pragma unroll
            for (int r = 0; r < 4; r++) acc[i][j][r] = 0.f;

    const __nv_bfloat16* Ag = g_A + (size_t)bm * KK;
    const __nv_bfloat16* Bg = g_B + (size_t)bn * KK;

    const int lrow = tid >> 1;              // 0..127
    const int lchunk = (tid & 1) * 4;       // 16B-chunk base (of 8 per row)

    const int nk = KK / BKg;                // 24

    auto issue_stage = [&](int kt, int s) {
        __nv_bfloat16* As = sm + s * STAGE;
        __nv_bfloat16* Bs = As + BM * LDSS;
        int k0 = kt * BKg;
        const __nv_bfloat16* a = Ag + (size_t)lrow * KK + k0 + lchunk * 8;
        const __nv_bfloat16* b = Bg + (size_t)lrow * KK + k0 + lchunk * 8;
        uint32_t da = (uint32_t)__cvta_generic_to_shared(As + lrow * LDSS + lchunk * 8);
        uint32_t db = (uint32_t)__cvta_generic_to_shared(Bs + lrow * LDSS + lchunk * 8);
#pragma unroll
        for (int i = 0; i < 4; i++) {
            asm volatile("cp.async.cg.shared.global [%0], [%1], 16;" :: "r"(da + i * 16), "l"(a + i * 8));
            asm volatile("cp.async.cg.shared.global [%0], [%1], 16;" :: "r"(db + i * 16), "l"(b + i * 8));
        }
        asm volatile("cp.async.commit_group;");
    };

    issue_stage(0, 0);

    const int arow = lane & 15;             // ldmatrix row within 16
    const int acol = (lane >> 4) * 8;       // ldmatrix 8-col half

    for (int kt = 0; kt < nk; kt++) {
        int s = kt & 1;
        if (kt + 1 < nk) {
            issue_stage(kt + 1, s ^ 1);
            asm volatile("cp.async.wait_group 1;");
        } else {
            asm volatile("cp.async.wait_group 0;");
        }
        __syncthreads();

        __nv_bfloat16* As = sm + s * STAGE;
        __nv_bfloat16* Bs = As + BM * LDSS;
        uint32_t a_base = (uint32_t)__cvta_generic_to_shared(
            As + (wm * 64 + arow) * LDSS + acol);
        uint32_t b_base = (uint32_t)__cvta_generic_to_shared(
            Bs + (wn * 32 + arow) * LDSS + acol);

#pragma unroll
        for (int k16 = 0; k16 < 4; k16++) {
            uint32_t af[4][4];
#pragma unroll
            for (int mi = 0; mi < 4; mi++)
                LDSM_X4(af[mi], a_base + (mi * 16 * LDSS + k16 * 16) * 2);
            uint32_t bf[2][4];
#pragma unroll
            for (int nj = 0; nj < 2; nj++)
                LDSM_X4(bf[nj], b_base + (nj * 16 * LDSS + k16 * 16) * 2);
#pragma unroll
            for (int mi = 0; mi < 4; mi++) {
#pragma unroll
                for (int ng = 0; ng < 4; ng++) {
                    int nj = ng >> 1, hi = ng & 1;
                    MMA_BF16(acc[mi][ng], af[mi], bf[nj][hi], bf[nj][hi + 2]);
                }
            }
        }
        __syncthreads();
    }

    // Epilogue: add bias, route cols [0,512) -> g_x1, [512,1024) -> g_x2
    const int row_t = lane >> 2;
    const int col_t = (lane & 3) * 2;
#pragma unroll
    for (int mi = 0; mi < 4; mi++) {
#pragma unroll
        for (int ng = 0; ng < 4; ng++) {
            int m = bm + wm * 64 + mi * 16 + row_t;
            int n = bn + wn * 32 + ng * 8 + col_t;
            float bi0 = g_bias[n], bi1 = g_bias[n + 1];
            float* dst = (n < Aq) ? g_x1 : g_x2;
            int nc = n & (Aq - 1);
            float2 v0 = make_float2(acc[mi][ng][0] + bi0, acc[mi][ng][1] + bi1);
            float2 v1 = make_float2(acc[mi][ng][2] + bi0, acc[mi][ng][3] + bi1);
            *(float2*)(dst + (size_t)m * Aq + nc) = v0;
            *(float2*)(dst + (size_t)(m + 8) * Aq + nc) = v1;
        }
    }
}

// ---------------- tanh + weighted reduction (unchanged from R1)
#define ROWS 32
#define RSTRIDE 516
#define SMEM_TANH ((2 * ROWS * RSTRIDE + Aq) * 4)

__global__ __launch_bounds__(256) void tanh_reduce(const float* __restrict__ Wout,
                                                   const float* __restrict__ bout,
                                                   float* __restrict__ out) {
    extern __shared__ float smf[];
    float* s1 = smf;
    float* s2 = smf + ROWS * RSTRIDE;
    float* sw = smf + 2 * ROWS * RSTRIDE;

    const int b  = blockIdx.z;
    const int it = blockIdx.y;
    const int jt = blockIdx.x;
    const int tid = threadIdx.x;
    const int j0base = jt * ROWS;
    const int i0base = it * ROWS;

    const float* x1b = g_x1 + (size_t)b * Nq * Aq;
    const float* x2b = g_x2 + (size_t)b * Nq * Aq;

    for (int idx = tid; idx < ROWS * (Aq / 4); idx += 256) {
        int row = idx >> 7;
        int c4  = idx & 127;
        *(float4*)(s1 + row * RSTRIDE + c4 * 4) =
            *(const float4*)(x1b + (j0base + row) * Aq + c4 * 4);
        int ii = i0base + row;
        float4 v = make_float4(0.f, 0.f, 0.f, 0.f);
        if (ii < Nq - 1) v = *(const float4*)(x2b + (ii + 1) * Aq + c4 * 4);
        *(float4*)(s2 + row * RSTRIDE + c4 * 4) = v;
    }
    if (tid < Aq / 4) *(float4*)(sw + tid * 4) = ((const float4*)Wout)[tid];
    __syncthreads();

    const int ti = tid >> 4;
    const int tj = tid & 15;

    const float* r1a = s1 + tj * RSTRIDE;
    const float* r1b = s1 + (tj + 16) * RSTRIDE;
    const float* r2a = s2 + ti * RSTRIDE;
    const float* r2b = s2 + (ti + 16) * RSTRIDE;

    float acc00 = 0.f, acc01 = 0.f, acc10 = 0.f, acc11 = 0.f;

#pragma unroll 2
    for (int a4 = 0; a4 < Aq / 4; a4++) {
        float4 w = *(const float4*)(sw + a4 * 4);
        float4 p = *(const float4*)(r1a + a4 * 4);
        float4 q = *(const float4*)(r1b + a4 * 4);
        float4 u = *(const float4*)(r2a + a4 * 4);
        float4 v = *(const float4*)(r2b + a4 * 4);

        acc00 += w.x * tanh_fast(u.x + p.x);
        acc00 += w.y * tanh_fast(u.y + p.y);
        acc00 += w.z * tanh_fast(u.z + p.z);
        acc00 += w.w * tanh_fast(u.w + p.w);

        acc01 += w.x * tanh_fast(u.x + q.x);
        acc01 += w.y * tanh_fast(u.y + q.y);
        acc01 += w.z * tanh_fast(u.z + q.z);
        acc01 += w.w * tanh_fast(u.w + q.w);

        acc10 += w.x * tanh_fast(v.x + p.x);
        acc10 += w.y * tanh_fast(v.y + p.y);
        acc10 += w.z * tanh_fast(v.z + p.z);
        acc10 += w.w * tanh_fast(v.w + p.w);

        acc11 += w.x * tanh_fast(v.x + q.x);
        acc11 += w.y * tanh_fast(v.y + q.y);
        acc11 += w.z * tanh_fast(v.z + q.z);
        acc11 += w.w * tanh_fast(v.w + q.w);
    }

    const float bo = bout[0];
    const int i0g = i0base + ti, i1g = i0g + 16;
    const int j0g = j0base + tj, j1g = j0g + 16;
    float* ob = out + (size_t)b * (Nq - 1) * Nq;

    if (i0g < Nq - 1) {
        ob[i0g * Nq + j0g] = acc00 + bo;
        ob[i0g * Nq + j1g] = acc01 + bo;
    }
    if (i1g < Nq - 1) {
        ob[i1g * Nq + j0g] = acc10 + bo;
        ob[i1g * Nq + j1g] = acc11 + bo;
    }
}

extern "C" void kernel_launch(void* const* d_in, const int* in_sizes, int n_in,
                              void* d_out, int out_size) {
    const float* x    = (const float*)d_in[0];
    const float* W1   = (const float*)d_in[1];
    const float* b1   = (const float*)d_in[2];
    const float* W2   = (const float*)d_in[3];
    const float* b2   = (const float*)d_in[4];
    const float* Wout = (const float*)d_in[5];
    const float* bout = (const float*)d_in[6];
    float* out = (float*)d_out;

    cudaFuncSetAttribute(tanh_reduce, cudaFuncAttributeMaxDynamicSharedMemorySize,
                         SMEM_TANH);
    cudaFuncSetAttribute(gemm_bf16, cudaFuncAttributeMaxDynamicSharedMemorySize,
                         SMEMG);

    split_x<<<(Mq * (Dq / 4) + 255) / 256, 256>>>(x);
    split_w<<<(NN * (Dq / 4) + 255) / 256, 256>>>(W1, W2, b1, b2);

    dim3 ggrid(NN / BN, Mq / BM);   // (8, 32)
    gemm_bf16<<<ggrid, 256, SMEMG>>>();

    dim3 tgrid(Nq / ROWS, Nq / ROWS, Bq);  // (4, 4, 32)
    tanh_reduce<<<tgrid, 256, SMEM_TANH>>>(Wout, bout, out);
}

// round 8
// speedup vs baseline: 1.5159x; 1.0576x over previous
#include <cuda_runtime.h>
#include <cuda_bf16.h>
#include <cstdint>

// Problem: B=32, N=128, D=512, A=512
//   x1 = x @ W1^T + b1   (B*N, A)
//   x2 = x @ W2^T + b2
//   out[b,i,j] = sum_a Wout[a]*tanh(x1[b,j,a] + x2[b,i+1,a]) + bout[0]
// GEMM via bf16 3-split tensor cores: A' = [hi|lo|hi] (K=1536), B' = [hi|hi|lo].

#define Bq 32
#define Nq 128
#define Dq 512
#define Aq 512
#define Mq (Bq*Nq)     // 4096
#define KK 1536        // 3*512 split-K
#define NN 1024        // two weight matrices stacked

__device__ float g_x1[Mq*Aq];
__device__ float g_x2[Mq*Aq];
__device__ __nv_bfloat16 g_A[(size_t)Mq*KK];   // x split   [4096][1536]
__device__ __nv_bfloat16 g_B[(size_t)NN*KK];   // W split   [1024][1536]
__device__ float g_bias[NN];

__device__ __forceinline__ float tanh_fast(float x) {
    float y;
    asm("tanh.approx.f32 %0, %1;" : "=f"(y) : "f"(x));
    return y;
}

__device__ __forceinline__ uint32_t pack_bf2(__nv_bfloat16 a, __nv_bfloat16 b) {
    return (uint32_t)__bfloat16_as_ushort(a) | ((uint32_t)__bfloat16_as_ushort(b) << 16);
}

// ---------------- split kernels (fp32 -> bf16 hi/lo, 3-way K layout)
__global__ __launch_bounds__(256) void split_x(const float* __restrict__ x) {
    int idx = blockIdx.x * 256 + threadIdx.x;
    if (idx >= Mq * (Dq / 4)) return;
    int m = idx >> 7;          // / 128
    int k4 = idx & 127;
    float4 v = ((const float4*)x)[idx];
    float vv[4] = {v.x, v.y, v.z, v.w};
    __nv_bfloat16 h[4], l[4];
#pragma unroll
    for (int i = 0; i < 4; i++) {
        h[i] = __float2bfloat16(vv[i]);
        l[i] = __float2bfloat16(vv[i] - __bfloat162float(h[i]));
    }
    uint2 hu, lu;
    hu.x = pack_bf2(h[0], h[1]); hu.y = pack_bf2(h[2], h[3]);
    lu.x = pack_bf2(l[0], l[1]); lu.y = pack_bf2(l[2], l[3]);
    __nv_bfloat16* dst = g_A + (size_t)m * KK + k4 * 4;
    *(uint2*)(dst)        = hu;   // k [0,512)    : hi
    *(uint2*)(dst + 512)  = lu;   // k [512,1024) : lo
    *(uint2*)(dst + 1024) = hu;   // k [1024,1536): hi
}

__global__ __launch_bounds__(256) void split_w(const float* __restrict__ W1,
                                               const float* __restrict__ W2,
                                               const float* __restrict__ b1,
                                               const float* __restrict__ b2) {
    int idx = blockIdx.x * 256 + threadIdx.x;
    if (idx < NN) g_bias[idx] = (idx < Aq) ? b1[idx] : b2[idx - Aq];
    if (idx >= NN * (Dq / 4)) return;
    int n = idx >> 7;
    int k4 = idx & 127;
    const float* src = (n < Aq) ? (W1 + (size_t)n * Dq) : (W2 + (size_t)(n - Aq) * Dq);
    float4 v = ((const float4*)src)[k4];
    float vv[4] = {v.x, v.y, v.z, v.w};
    __nv_bfloat16 h[4], l[4];
#pragma unroll
    for (int i = 0; i < 4; i++) {
        h[i] = __float2bfloat16(vv[i]);
        l[i] = __float2bfloat16(vv[i] - __bfloat162float(h[i]));
    }
    uint2 hu, lu;
    hu.x = pack_bf2(h[0], h[1]); hu.y = pack_bf2(h[2], h[3]);
    lu.x = pack_bf2(l[0], l[1]); lu.y = pack_bf2(l[2], l[3]);
    __nv_bfloat16* dst = g_B + (size_t)n * KK + k4 * 4;
    *(uint2*)(dst)        = hu;   // hi
    *(uint2*)(dst + 512)  = hu;   // hi (pairs with A lo)
    *(uint2*)(dst + 1024) = lu;   // lo (pairs with A hi)
}

// ---------------- bf16 tensor-core GEMM: C[m,n] = sum_k A'[m,k]*B'[n,k] + bias[n]
#define BM 128
#define BN 128
#define BKg 64
#define LDSS 72                    // padded smem row stride (bf16 elems)
#define STAGE ((BM + BN) * LDSS)   // elems per stage
#define SMEMG (2 * STAGE * 2)      // bytes (2 stages)

#define LDSM_X4(r, addr) \
    asm volatile("ldmatrix.sync.aligned.m8n8.x4.shared.b16 {%0,%1,%2,%3}, [%4];" \
                 : "=r"((r)[0]), "=r"((r)[1]), "=r"((r)[2]), "=r"((r)[3]) : "r"(addr))

#define MMA_BF16(d, a, b0, b1) \
    asm volatile("mma.sync.aligned.m16n8k16.row.col.f32.bf16.bf16.f32 " \
                 "{%0,%1,%2,%3}, {%4,%5,%6,%7}, {%8,%9}, {%0,%1,%2,%3};" \
                 : "+f"((d)[0]), "+f"((d)[1]), "+f"((d)[2]), "+f"((d)[3]) \
                 : "r"((a)[0]), "r"((a)[1]), "r"((a)[2]), "r"((a)[3]), "r"(b0), "r"(b1))

__global__ __launch_bounds__(256, 2) void gemm_bf16() {
    extern __shared__ __nv_bfloat16 sm[];
    const int tid = threadIdx.x;
    const int warp = tid >> 5, lane = tid & 31;
    const int wm = warp & 1;        // 0..1 -> 64-row slab
    const int wn = warp >> 1;       // 0..3 -> 32-col slab
    const int bm = blockIdx.y * BM;
    const int bn = blockIdx.x * BN;

    float acc[4][4][4];
#pragma unroll
    for (int i = 0; i < 4; i++)
#pragma unroll
        for (int j = 0; j < 4; j++)
#pragma unroll
            for (int r = 0; r < 4; r++) acc[i][j][r] = 0.f;

    const __nv_bfloat16* Ag = g_A + (size_t)bm * KK;
    const __nv_bfloat16* Bg = g_B + (size_t)bn * KK;

    const int lrow = tid >> 1;              // 0..127
    const int lchunk = (tid & 1) * 4;       // 16B-chunk base (of 8 per row)

    const int nk = KK / BKg;                // 24

    auto issue_stage = [&](int kt, int s) {
        __nv_bfloat16* As = sm + s * STAGE;
        __nv_bfloat16* Bs = As + BM * LDSS;
        int k0 = kt * BKg;
        const __nv_bfloat16* a = Ag + (size_t)lrow * KK + k0 + lchunk * 8;
        const __nv_bfloat16* b = Bg + (size_t)lrow * KK + k0 + lchunk * 8;
        uint32_t da = (uint32_t)__cvta_generic_to_shared(As + lrow * LDSS + lchunk * 8);
        uint32_t db = (uint32_t)__cvta_generic_to_shared(Bs + lrow * LDSS + lchunk * 8);
#pragma unroll
        for (int i = 0; i < 4; i++) {
            asm volatile("cp.async.cg.shared.global [%0], [%1], 16;" :: "r"(da + i * 16), "l"(a + i * 8));
            asm volatile("cp.async.cg.shared.global [%0], [%1], 16;" :: "r"(db + i * 16), "l"(b + i * 8));
        }
        asm volatile("cp.async.commit_group;");
    };

    issue_stage(0, 0);

    const int arow = lane & 15;
    const int acol = (lane >> 4) * 8;

    for (int kt = 0; kt < nk; kt++) {
        int s = kt & 1;
        if (kt + 1 < nk) {
            issue_stage(kt + 1, s ^ 1);
            asm volatile("cp.async.wait_group 1;");
        } else {
            asm volatile("cp.async.wait_group 0;");
        }
        __syncthreads();

        __nv_bfloat16* As = sm + s * STAGE;
        __nv_bfloat16* Bs = As + BM * LDSS;
        uint32_t a_base = (uint32_t)__cvta_generic_to_shared(
            As + (wm * 64 + arow) * LDSS + acol);
        uint32_t b_base = (uint32_t)__cvta_generic_to_shared(
            Bs + (wn * 32 + arow) * LDSS + acol);

#pragma unroll
        for (int k16 = 0; k16 < 4; k16++) {
            uint32_t af[4][4];
#pragma unroll
            for (int mi = 0; mi < 4; mi++)
                LDSM_X4(af[mi], a_base + (mi * 16 * LDSS + k16 * 16) * 2);
            uint32_t bf[2][4];
#pragma unroll
            for (int nj = 0; nj < 2; nj++)
                LDSM_X4(bf[nj], b_base + (nj * 16 * LDSS + k16 * 16) * 2);
#pragma unroll
            for (int mi = 0; mi < 4; mi++) {
#pragma unroll
                for (int ng = 0; ng < 4; ng++) {
                    int nj = ng >> 1, hi = ng & 1;
                    MMA_BF16(acc[mi][ng], af[mi], bf[nj][hi], bf[nj][hi + 2]);
                }
            }
        }
        __syncthreads();
    }

    const int row_t = lane >> 2;
    const int col_t = (lane & 3) * 2;
#pragma unroll
    for (int mi = 0; mi < 4; mi++) {
#pragma unroll
        for (int ng = 0; ng < 4; ng++) {
            int m = bm + wm * 64 + mi * 16 + row_t;
            int n = bn + wn * 32 + ng * 8 + col_t;
            float bi0 = g_bias[n], bi1 = g_bias[n + 1];
            float* dst = (n < Aq) ? g_x1 : g_x2;
            int nc = n & (Aq - 1);
            float2 v0 = make_float2(acc[mi][ng][0] + bi0, acc[mi][ng][1] + bi1);
            float2 v1 = make_float2(acc[mi][ng][2] + bi0, acc[mi][ng][3] + bi1);
            *(float2*)(dst + (size_t)m * Aq + nc) = v0;
            *(float2*)(dst + (size_t)(m + 8) * Aq + nc) = v1;
        }
    }
}

// ---------------- tanh + weighted reduction (v2)
// x1 j-rows staged in smem (reused 16x across i); x2 i-rows read via __ldg
// (uniform address across 16 tj-threads -> L1 broadcast). smem 68 KB ->
// 3 blocks/SM, 24 warps: MUFU-pipe saturation instead of 8-warp latency bind.
#define ROWS 32
#define RSTRIDE 516
#define SMEM_TANH ((ROWS * RSTRIDE + Aq) * 4)

__global__ __launch_bounds__(256, 3) void tanh_reduce(const float* __restrict__ Wout,
                                                      const float* __restrict__ bout,
                                                      float* __restrict__ out) {
    extern __shared__ float smf[];
    float* s1 = smf;                   // [32][516] x1 rows (j)
    float* sw = smf + ROWS * RSTRIDE;  // [512] Wout

    const int b  = blockIdx.z;
    const int it = blockIdx.y;
    const int jt = blockIdx.x;
    const int tid = threadIdx.x;
    const int j0base = jt * ROWS;
    const int i0base = it * ROWS;

    const float* x1b = g_x1 + (size_t)b * Nq * Aq;
    const float* x2b = g_x2 + (size_t)b * Nq * Aq;

    // Stage 32 x1 rows + Wout.
    for (int idx = tid; idx < ROWS * (Aq / 4); idx += 256) {
        int row = idx >> 7;
        int c4  = idx & 127;
        *(float4*)(s1 + row * RSTRIDE + c4 * 4) =
            *(const float4*)(x1b + (j0base + row) * Aq + c4 * 4);
    }
    if (tid < Aq / 4) *(float4*)(sw + tid * 4) = ((const float4*)Wout)[tid];
    __syncthreads();

    const int ti = tid >> 4;   // 0..15
    const int tj = tid & 15;   // 0..15

    const float* r1a = s1 + tj * RSTRIDE;
    const float* r1b = s1 + (tj + 16) * RSTRIDE;

    const int i0g = i0base + ti;        // <= 111, always valid
    const int i1g = i0g + 16;           // <= 127; row i1g+1 OOB only when ==127
    const float4* r2a = (const float4*)(x2b + (size_t)(i0g + 1) * Aq);
    const float4* r2b = (const float4*)(x2b +
        (size_t)((i1g < Nq - 1) ? (i1g + 1) : 0) * Aq);

    float acc00 = 0.f, acc01 = 0.f, acc10 = 0.f, acc11 = 0.f;

#pragma unroll 2
    for (int a4 = 0; a4 < Aq / 4; a4++) {
        float4 w = *(const float4*)(sw + a4 * 4);
        float4 p = *(const float4*)(r1a + 0) ; p = *(const float4*)(r1a + 0);
        p = ((const float4*)r1a)[a4];
        float4 q = ((const float4*)r1b)[a4];
        float4 u = __ldg(r2a + a4);   // x2[i0+1]
        float4 v = __ldg(r2b + a4);   // x2[i1+1]

        acc00 += w.x * tanh_fast(u.x + p.x);
        acc00 += w.y * tanh_fast(u.y + p.y);
        acc00 += w.z * tanh_fast(u.z + p.z);
        acc00 += w.w * tanh_fast(u.w + p.w);

        acc01 += w.x * tanh_fast(u.x + q.x);
        acc01 += w.y * tanh_fast(u.y + q.y);
        acc01 += w.z * tanh_fast(u.z + q.z);
        acc01 += w.w * tanh_fast(u.w + q.w);

        acc10 += w.x * tanh_fast(v.x + p.x);
        acc10 += w.y * tanh_fast(v.y + p.y);
        acc10 += w.z * tanh_fast(v.z + p.z);
        acc10 += w.w * tanh_fast(v.w + p.w);

        acc11 += w.x * tanh_fast(v.x + q.x);
        acc11 += w.y * tanh_fast(v.y + q.y);
        acc11 += w.z * tanh_fast(v.z + q.z);
        acc11 += w.w * tanh_fast(v.w + q.w);
    }

    const float bo = bout[0];
    const int j0g = j0base + tj, j1g = j0g + 16;
    float* ob = out + (size_t)b * (Nq - 1) * Nq;

    ob[i0g * Nq + j0g] = acc00 + bo;
    ob[i0g * Nq + j1g] = acc01 + bo;
    if (i1g < Nq - 1) {
        ob[i1g * Nq + j0g] = acc10 + bo;
        ob[i1g * Nq + j1g] = acc11 + bo;
    }
}

extern "C" void kernel_launch(void* const* d_in, const int* in_sizes, int n_in,
                              void* d_out, int out_size) {
    const float* x    = (const float*)d_in[0];
    const float* W1   = (const float*)d_in[1];
    const float* b1   = (const float*)d_in[2];
    const float* W2   = (const float*)d_in[3];
    const float* b2   = (const float*)d_in[4];
    const float* Wout = (const float*)d_in[5];
    const float* bout = (const float*)d_in[6];
    float* out = (float*)d_out;

    cudaFuncSetAttribute(tanh_reduce, cudaFuncAttributeMaxDynamicSharedMemorySize,
                         SMEM_TANH);
    cudaFuncSetAttribute(gemm_bf16, cudaFuncAttributeMaxDynamicSharedMemorySize,
                         SMEMG);

    split_x<<<(Mq * (Dq / 4) + 255) / 256, 256>>>(x);
    split_w<<<(NN * (Dq / 4) + 255) / 256, 256>>>(W1, W2, b1, b2);

    dim3 ggrid(NN / BN, Mq / BM);   // (8, 32)
    gemm_bf16<<<ggrid, 256, SMEMG>>>();

    dim3 tgrid(Nq / ROWS, Nq / ROWS, Bq);  // (4, 4, 32)
    tanh_reduce<<<tgrid, 256, SMEM_TANH>>>(Wout, bout, out);
}

// round 12
// speedup vs baseline: 1.6332x; 1.0774x over previous
#include <cuda_runtime.h>
#include <cuda_bf16.h>
#include <cstdint>

// Problem: B=32, N=128, D=512, A=512
//   x1 = x @ W1^T + b1   (B*N, A)
//   x2 = x @ W2^T + b2
//   out[b,i,j] = sum_a Wout[a]*tanh(x1[b,j,a] + x2[b,i+1,a]) + bout[0]
// GEMM via bf16 3-split tensor cores: A' = [hi|lo|hi] (K=1536), B' = [hi|hi|lo].

#define Bq 32
#define Nq 128
#define Dq 512
#define Aq 512
#define Mq (Bq*Nq)     // 4096
#define KK 1536        // 3*512 split-K
#define NN 1024        // two weight matrices stacked

__device__ float g_x1[Mq*Aq];
__device__ float g_x2[Mq*Aq];
__device__ __nv_bfloat16 g_A[(size_t)Mq*KK];   // x split   [4096][1536]
__device__ __nv_bfloat16 g_B[(size_t)NN*KK];   // W split   [1024][1536]
__device__ float g_bias[NN];

__device__ __forceinline__ float tanh_fast(float x) {
    float y;
    asm("tanh.approx.f32 %0, %1;" : "=f"(y) : "f"(x));
    return y;
}

__device__ __forceinline__ uint32_t pack_bf2(__nv_bfloat16 a, __nv_bfloat16 b) {
    return (uint32_t)__bfloat16_as_ushort(a) | ((uint32_t)__bfloat16_as_ushort(b) << 16);
}

// ---------------- split kernels (fp32 -> bf16 hi/lo, 3-way K layout)
__global__ __launch_bounds__(256) void split_x(const float* __restrict__ x) {
    int idx = blockIdx.x * 256 + threadIdx.x;
    if (idx >= Mq * (Dq / 4)) return;
    int m = idx >> 7;          // / 128
    int k4 = idx & 127;
    float4 v = ((const float4*)x)[idx];
    float vv[4] = {v.x, v.y, v.z, v.w};
    __nv_bfloat16 h[4], l[4];
#pragma unroll
    for (int i = 0; i < 4; i++) {
        h[i] = __float2bfloat16(vv[i]);
        l[i] = __float2bfloat16(vv[i] - __bfloat162float(h[i]));
    }
    uint2 hu, lu;
    hu.x = pack_bf2(h[0], h[1]); hu.y = pack_bf2(h[2], h[3]);
    lu.x = pack_bf2(l[0], l[1]); lu.y = pack_bf2(l[2], l[3]);
    __nv_bfloat16* dst = g_A + (size_t)m * KK + k4 * 4;
    *(uint2*)(dst)        = hu;   // k [0,512)    : hi
    *(uint2*)(dst + 512)  = lu;   // k [512,1024) : lo
    *(uint2*)(dst + 1024) = hu;   // k [1024,1536): hi
}

__global__ __launch_bounds__(256) void split_w(const float* __restrict__ W1,
                                               const float* __restrict__ W2,
                                               const float* __restrict__ b1,
                                               const float* __restrict__ b2) {
    int idx = blockIdx.x * 256 + threadIdx.x;
    if (idx < NN) g_bias[idx] = (idx < Aq) ? b1[idx] : b2[idx - Aq];
    if (idx >= NN * (Dq / 4)) return;
    int n = idx >> 7;
    int k4 = idx & 127;
    const float* src = (n < Aq) ? (W1 + (size_t)n * Dq) : (W2 + (size_t)(n - Aq) * Dq);
    float4 v = ((const float4*)src)[k4];
    float vv[4] = {v.x, v.y, v.z, v.w};
    __nv_bfloat16 h[4], l[4];
#pragma unroll
    for (int i = 0; i < 4; i++) {
        h[i] = __float2bfloat16(vv[i]);
        l[i] = __float2bfloat16(vv[i] - __bfloat162float(h[i]));
    }
    uint2 hu, lu;
    hu.x = pack_bf2(h[0], h[1]); hu.y = pack_bf2(h[2], h[3]);
    lu.x = pack_bf2(l[0], l[1]); lu.y = pack_bf2(l[2], l[3]);
    __nv_bfloat16* dst = g_B + (size_t)n * KK + k4 * 4;
    *(uint2*)(dst)        = hu;   // hi
    *(uint2*)(dst + 512)  = hu;   // hi (pairs with A lo)
    *(uint2*)(dst + 1024) = lu;   // lo (pairs with A hi)
}

// ---------------- bf16 tensor-core GEMM: C[m,n] = sum_k A'[m,k]*B'[n,k] + bias[n]
#define BM 128
#define BN 128
#define BKg 64
#define LDSS 72                    // padded smem row stride (bf16 elems)
#define STAGE ((BM + BN) * LDSS)   // elems per stage
#define SMEMG (2 * STAGE * 2)      // bytes (2 stages)

#define LDSM_X4(r, addr) \
    asm volatile("ldmatrix.sync.aligned.m8n8.x4.shared.b16 {%0,%1,%2,%3}, [%4];" \
                 : "=r"((r)[0]), "=r"((r)[1]), "=r"((r)[2]), "=r"((r)[3]) : "r"(addr))

#define MMA_BF16(d, a, b0, b1) \
    asm volatile("mma.sync.aligned.m16n8k16.row.col.f32.bf16.bf16.f32 " \
                 "{%0,%1,%2,%3}, {%4,%5,%6,%7}, {%8,%9}, {%0,%1,%2,%3};" \
                 : "+f"((d)[0]), "+f"((d)[1]), "+f"((d)[2]), "+f"((d)[3]) \
                 : "r"((a)[0]), "r"((a)[1]), "r"((a)[2]), "r"((a)[3]), "r"(b0), "r"(b1))

__global__ __launch_bounds__(256, 2) void gemm_bf16() {
    extern __shared__ __nv_bfloat16 sm[];
    const int tid = threadIdx.x;
    const int warp = tid >> 5, lane = tid & 31;
    const int wm = warp & 1;        // 0..1 -> 64-row slab
    const int wn = warp >> 1;       // 0..3 -> 32-col slab
    const int bm = blockIdx.y * BM;
    const int bn = blockIdx.x * BN;

    float acc[4][4][4];
#pragma unroll
    for (int i = 0; i < 4; i++)
#pragma unroll
        for (int j = 0; j < 4; j++)
#pragma unroll
            for (int r = 0; r < 4; r++) acc[i][j][r] = 0.f;

    const __nv_bfloat16* Ag = g_A + (size_t)bm * KK;
    const __nv_bfloat16* Bg = g_B + (size_t)bn * KK;

    const int lrow = tid >> 1;              // 0..127
    const int lchunk = (tid & 1) * 4;       // 16B-chunk base (of 8 per row)

    const int nk = KK / BKg;                // 24

    auto issue_stage = [&](int kt, int s) {
        __nv_bfloat16* As = sm + s * STAGE;
        __nv_bfloat16* Bs = As + BM * LDSS;
        int k0 = kt * BKg;
        const __nv_bfloat16* a = Ag + (size_t)lrow * KK + k0 + lchunk * 8;
        const __nv_bfloat16* b = Bg + (size_t)lrow * KK + k0 + lchunk * 8;
        uint32_t da = (uint32_t)__cvta_generic_to_shared(As + lrow * LDSS + lchunk * 8);
        uint32_t db = (uint32_t)__cvta_generic_to_shared(Bs + lrow * LDSS + lchunk * 8);
#pragma unroll
        for (int i = 0; i < 4; i++) {
            asm volatile("cp.async.cg.shared.global [%0], [%1], 16;" :: "r"(da + i * 16), "l"(a + i * 8));
            asm volatile("cp.async.cg.shared.global [%0], [%1], 16;" :: "r"(db + i * 16), "l"(b + i * 8));
        }
        asm volatile("cp.async.commit_group;");
    };

    issue_stage(0, 0);

    const int arow = lane & 15;
    const int acol = (lane >> 4) * 8;

    for (int kt = 0; kt < nk; kt++) {
        int s = kt & 1;
        if (kt + 1 < nk) {
            issue_stage(kt + 1, s ^ 1);
            asm volatile("cp.async.wait_group 1;");
        } else {
            asm volatile("cp.async.wait_group 0;");
        }
        __syncthreads();

        __nv_bfloat16* As = sm + s * STAGE;
        __nv_bfloat16* Bs = As + BM * LDSS;
        uint32_t a_base = (uint32_t)__cvta_generic_to_shared(
            As + (wm * 64 + arow) * LDSS + acol);
        uint32_t b_base = (uint32_t)__cvta_generic_to_shared(
            Bs + (wn * 32 + arow) * LDSS + acol);

#pragma unroll
        for (int k16 = 0; k16 < 4; k16++) {
            uint32_t af[4][4];
#pragma unroll
            for (int mi = 0; mi < 4; mi++)
                LDSM_X4(af[mi], a_base + (mi * 16 * LDSS + k16 * 16) * 2);
            uint32_t bf[2][4];
#pragma unroll
            for (int nj = 0; nj < 2; nj++)
                LDSM_X4(bf[nj], b_base + (nj * 16 * LDSS + k16 * 16) * 2);
#pragma unroll
            for (int mi = 0; mi < 4; mi++) {
#pragma unroll
                for (int ng = 0; ng < 4; ng++) {
                    int nj = ng >> 1, hi = ng & 1;
                    MMA_BF16(acc[mi][ng], af[mi], bf[nj][hi], bf[nj][hi + 2]);
                }
            }
        }
        __syncthreads();
    }

    const int row_t = lane >> 2;
    const int col_t = (lane & 3) * 2;
#pragma unroll
    for (int mi = 0; mi < 4; mi++) {
#pragma unroll
        for (int ng = 0; ng < 4; ng++) {
            int m = bm + wm * 64 + mi * 16 + row_t;
            int n = bn + wn * 32 + ng * 8 + col_t;
            float bi0 = g_bias[n], bi1 = g_bias[n + 1];
            float* dst = (n < Aq) ? g_x1 : g_x2;
            int nc = n & (Aq - 1);
            float2 v0 = make_float2(acc[mi][ng][0] + bi0, acc[mi][ng][1] + bi1);
            float2 v1 = make_float2(acc[mi][ng][2] + bi0, acc[mi][ng][3] + bi1);
            *(float2*)(dst + (size_t)m * Aq + nc) = v0;
            *(float2*)(dst + (size_t)(m + 8) * Aq + nc) = v1;
        }
    }
}

// ---------------- tanh + weighted reduction (v3)
// 512 threads, tile 64 i x 32 j per block -> grid 256 blocks = ONE wave at
// 2 blocks/SM (smem 68KB x2 = 136KB <= 227KB). x1 j-rows in smem (reused 32x),
// x2 i-rows via __ldg L1 broadcast. Each thread: 2x2 (i,j) microtile.
#define ROWS 32
#define ITILE 64
#define RSTRIDE 516
#define SMEM_TANH ((ROWS * RSTRIDE + Aq) * 4)

__global__ __launch_bounds__(512, 2) void tanh_reduce(const float* __restrict__ Wout,
                                                      const float* __restrict__ bout,
                                                      float* __restrict__ out) {
    extern __shared__ float smf[];
    float* s1 = smf;                   // [32][516] x1 rows (j)
    float* sw = smf + ROWS * RSTRIDE;  // [512] Wout

    const int b  = blockIdx.z;
    const int it = blockIdx.y;
    const int jt = blockIdx.x;
    const int tid = threadIdx.x;
    const int j0base = jt * ROWS;
    const int i0base = it * ITILE;

    const float* x1b = g_x1 + (size_t)b * Nq * Aq;
    const float* x2b = g_x2 + (size_t)b * Nq * Aq;

    // Stage 32 x1 rows + Wout.
    for (int idx = tid; idx < ROWS * (Aq / 4); idx += 512) {
        int row = idx >> 7;
        int c4  = idx & 127;
        *(float4*)(s1 + row * RSTRIDE + c4 * 4) =
            *(const float4*)(x1b + (j0base + row) * Aq + c4 * 4);
    }
    if (tid < Aq / 4) *(float4*)(sw + tid * 4) = ((const float4*)Wout)[tid];
    __syncthreads();

    const int ti = tid >> 4;   // 0..31
    const int tj = tid & 15;   // 0..15

    const float* r1a = s1 + tj * RSTRIDE;
    const float* r1b = s1 + (tj + 16) * RSTRIDE;

    const int i0g = i0base + ti;        // <= 95, always valid
    const int i1g = i0g + 32;           // <= 127; row i1g+1 OOB only when ==127
    const float4* r2a = (const float4*)(x2b + (size_t)(i0g + 1) * Aq);
    const float4* r2b = (const float4*)(x2b +
        (size_t)((i1g < Nq - 1) ? (i1g + 1) : 0) * Aq);

    float acc00 = 0.f, acc01 = 0.f, acc10 = 0.f, acc11 = 0.f;

#pragma unroll 2
    for (int a4 = 0; a4 < Aq / 4; a4++) {
        float4 w = *(const float4*)(sw + a4 * 4);
        float4 p = ((const float4*)r1a)[a4];   // x1[j0]
        float4 q = ((const float4*)r1b)[a4];   // x1[j1]
        float4 u = __ldg(r2a + a4);            // x2[i0+1]
        float4 v = __ldg(r2b + a4);            // x2[i1+1]

        acc00 += w.x * tanh_fast(u.x + p.x);
        acc00 += w.y * tanh_fast(u.y + p.y);
        acc00 += w.z * tanh_fast(u.z + p.z);
        acc00 += w.w * tanh_fast(u.w + p.w);

        acc01 += w.x * tanh_fast(u.x + q.x);
        acc01 += w.y * tanh_fast(u.y + q.y);
        acc01 += w.z * tanh_fast(u.z + q.z);
        acc01 += w.w * tanh_fast(u.w + q.w);

        acc10 += w.x * tanh_fast(v.x + p.x);
        acc10 += w.y * tanh_fast(v.y + p.y);
        acc10 += w.z * tanh_fast(v.z + p.z);
        acc10 += w.w * tanh_fast(v.w + p.w);

        acc11 += w.x * tanh_fast(v.x + q.x);
        acc11 += w.y * tanh_fast(v.y + q.y);
        acc11 += w.z * tanh_fast(v.z + q.z);
        acc11 += w.w * tanh_fast(v.w + q.w);
    }

    const float bo = bout[0];
    const int j0g = j0base + tj, j1g = j0g + 16;
    float* ob = out + (size_t)b * (Nq - 1) * Nq;

    ob[i0g * Nq + j0g] = acc00 + bo;
    ob[i0g * Nq + j1g] = acc01 + bo;
    if (i1g < Nq - 1) {
        ob[i1g * Nq + j0g] = acc10 + bo;
        ob[i1g * Nq + j1g] = acc11 + bo;
    }
}

extern "C" void kernel_launch(void* const* d_in, const int* in_sizes, int n_in,
                              void* d_out, int out_size) {
    const float* x    = (const float*)d_in[0];
    const float* W1   = (const float*)d_in[1];
    const float* b1   = (const float*)d_in[2];
    const float* W2   = (const float*)d_in[3];
    const float* b2   = (const float*)d_in[4];
    const float* Wout = (const float*)d_in[5];
    const float* bout = (const float*)d_in[6];
    float* out = (float*)d_out;

    cudaFuncSetAttribute(tanh_reduce, cudaFuncAttributeMaxDynamicSharedMemorySize,
                         SMEM_TANH);
    cudaFuncSetAttribute(gemm_bf16, cudaFuncAttributeMaxDynamicSharedMemorySize,
                         SMEMG);

    split_x<<<(Mq * (Dq / 4) + 255) / 256, 256>>>(x);
    split_w<<<(NN * (Dq / 4) + 255) / 256, 256>>>(W1, W2, b1, b2);

    dim3 ggrid(NN / BN, Mq / BM);   // (8, 32)
    gemm_bf16<<<ggrid, 256, SMEMG>>>();

    dim3 tgrid(Nq / ROWS, Nq / ITILE, Bq);  // (4, 2, 32) = 256 blocks
    tanh_reduce<<<tgrid, 512, SMEM_TANH>>>(Wout, bout, out);
}

// round 13
// speedup vs baseline: 1.6568x; 1.0145x over previous
#include <cuda_runtime.h>
#include <cuda_bf16.h>
#include <cuda_fp16.h>
#include <cstdint>

// Problem: B=32, N=128, D=512, A=512
//   x1 = x @ W1^T + b1   (B*N, A)
//   x2 = x @ W2^T + b2
//   out[b,i,j] = sum_a Wout[a]*tanh(x1[b,j,a] + x2[b,i+1,a]) + bout[0]
// GEMM via bf16 3-split tensor cores; x1/x2 stored as f16; tanh via
// tanh.approx.f16x2 (2 elems per MUFU op), f32 Wout + f32 accumulation.

#define Bq 32
#define Nq 128
#define Dq 512
#define Aq 512
#define Mq (Bq*Nq)     // 4096
#define KK 1536        // 3*512 split-K
#define NN 1024        // two weight matrices stacked

__device__ __half g_x1h[Mq*Aq];
__device__ __half g_x2h[Mq*Aq];
__device__ __nv_bfloat16 g_A[(size_t)Mq*KK];   // x split   [4096][1536]
__device__ __nv_bfloat16 g_B[(size_t)NN*KK];   // W split   [1024][1536]
__device__ float g_bias[NN];

__device__ __forceinline__ uint32_t htanh2(uint32_t x) {
    uint32_t y;
    asm("tanh.approx.f16x2 %0, %1;" : "=r"(y) : "r"(x));
    return y;
}

__device__ __forceinline__ uint32_t hadd2u(uint32_t a, uint32_t b) {
    uint32_t y;
    asm("add.f16x2 %0, %1, %2;" : "=r"(y) : "r"(a), "r"(b));
    return y;
}

__device__ __forceinline__ float2 h2_to_f2(uint32_t h) {
    __half2 hh = *(const __half2*)&h;
    return __half22float2(hh);
}

__device__ __forceinline__ uint32_t pack_bf2(__nv_bfloat16 a, __nv_bfloat16 b) {
    return (uint32_t)__bfloat16_as_ushort(a) | ((uint32_t)__bfloat16_as_ushort(b) << 16);
}

// ---------------- split kernels (fp32 -> bf16 hi/lo, 3-way K layout)
__global__ __launch_bounds__(256) void split_x(const float* __restrict__ x) {
    int idx = blockIdx.x * 256 + threadIdx.x;
    if (idx >= Mq * (Dq / 4)) return;
    int m = idx >> 7;          // / 128
    int k4 = idx & 127;
    float4 v = ((const float4*)x)[idx];
    float vv[4] = {v.x, v.y, v.z, v.w};
    __nv_bfloat16 h[4], l[4];
#pragma unroll
    for (int i = 0; i < 4; i++) {
        h[i] = __float2bfloat16(vv[i]);
        l[i] = __float2bfloat16(vv[i] - __bfloat162float(h[i]));
    }
    uint2 hu, lu;
    hu.x = pack_bf2(h[0], h[1]); hu.y = pack_bf2(h[2], h[3]);
    lu.x = pack_bf2(l[0], l[1]); lu.y = pack_bf2(l[2], l[3]);
    __nv_bfloat16* dst = g_A + (size_t)m * KK + k4 * 4;
    *(uint2*)(dst)        = hu;   // k [0,512)    : hi
    *(uint2*)(dst + 512)  = lu;   // k [512,1024) : lo
    *(uint2*)(dst + 1024) = hu;   // k [1024,1536): hi
}

__global__ __launch_bounds__(256) void split_w(const float* __restrict__ W1,
                                               const float* __restrict__ W2,
                                               const float* __restrict__ b1,
                                               const float* __restrict__ b2) {
    int idx = blockIdx.x * 256 + threadIdx.x;
    if (idx < NN) g_bias[idx] = (idx < Aq) ? b1[idx] : b2[idx - Aq];
    if (idx >= NN * (Dq / 4)) return;
    int n = idx >> 7;
    int k4 = idx & 127;
    const float* src = (n < Aq) ? (W1 + (size_t)n * Dq) : (W2 + (size_t)(n - Aq) * Dq);
    float4 v = ((const float4*)src)[k4];
    float vv[4] = {v.x, v.y, v.z, v.w};
    __nv_bfloat16 h[4], l[4];
#pragma unroll
    for (int i = 0; i < 4; i++) {
        h[i] = __float2bfloat16(vv[i]);
        l[i] = __float2bfloat16(vv[i] - __bfloat162float(h[i]));
    }
    uint2 hu, lu;
    hu.x = pack_bf2(h[0], h[1]); hu.y = pack_bf2(h[2], h[3]);
    lu.x = pack_bf2(l[0], l[1]); lu.y = pack_bf2(l[2], l[3]);
    __nv_bfloat16* dst = g_B + (size_t)n * KK + k4 * 4;
    *(uint2*)(dst)        = hu;   // hi
    *(uint2*)(dst + 512)  = hu;   // hi (pairs with A lo)
    *(uint2*)(dst + 1024) = lu;   // lo (pairs with A hi)
}

// ---------------- bf16 tensor-core GEMM: C[m,n] = sum_k A'[m,k]*B'[n,k] + bias[n]
#define BM 128
#define BN 128
#define BKg 64
#define LDSS 72                    // padded smem row stride (bf16 elems)
#define STAGE ((BM + BN) * LDSS)   // elems per stage
#define SMEMG (2 * STAGE * 2)      // bytes (2 stages)

#define LDSM_X4(r, addr) \
    asm volatile("ldmatrix.sync.aligned.m8n8.x4.shared.b16 {%0,%1,%2,%3}, [%4];" \
                 : "=r"((r)[0]), "=r"((r)[1]), "=r"((r)[2]), "=r"((r)[3]) : "r"(addr))

#define MMA_BF16(d, a, b0, b1) \
    asm volatile("mma.sync.aligned.m16n8k16.row.col.f32.bf16.bf16.f32 " \
                 "{%0,%1,%2,%3}, {%4,%5,%6,%7}, {%8,%9}, {%0,%1,%2,%3};" \
                 : "+f"((d)[0]), "+f"((d)[1]), "+f"((d)[2]), "+f"((d)[3]) \
                 : "r"((a)[0]), "r"((a)[1]), "r"((a)[2]), "r"((a)[3]), "r"(b0), "r"(b1))

__global__ __launch_bounds__(256, 2) void gemm_bf16() {
    extern __shared__ __nv_bfloat16 sm[];
    const int tid = threadIdx.x;
    const int warp = tid >> 5, lane = tid & 31;
    const int wm = warp & 1;
    const int wn = warp >> 1;
    const int bm = blockIdx.y * BM;
    const int bn = blockIdx.x * BN;

    float acc[4][4][4];
#pragma unroll
    for (int i = 0; i < 4; i++)
#pragma unroll
        for (int j = 0; j < 4; j++)
#pragma unroll
            for (int r = 0; r < 4; r++) acc[i][j][r] = 0.f;

    const __nv_bfloat16* Ag = g_A + (size_t)bm * KK;
    const __nv_bfloat16* Bg = g_B + (size_t)bn * KK;

    const int lrow = tid >> 1;
    const int lchunk = (tid & 1) * 4;
    const int nk = KK / BKg;                // 24

    auto issue_stage = [&](int kt, int s) {
        __nv_bfloat16* As = sm + s * STAGE;
        __nv_bfloat16* Bs = As + BM * LDSS;
        int k0 = kt * BKg;
        const __nv_bfloat16* a = Ag + (size_t)lrow * KK + k0 + lchunk * 8;
        const __nv_bfloat16* b = Bg + (size_t)lrow * KK + k0 + lchunk * 8;
        uint32_t da = (uint32_t)__cvta_generic_to_shared(As + lrow * LDSS + lchunk * 8);
        uint32_t db = (uint32_t)__cvta_generic_to_shared(Bs + lrow * LDSS + lchunk * 8);
#pragma unroll
        for (int i = 0; i < 4; i++) {
            asm volatile("cp.async.cg.shared.global [%0], [%1], 16;" :: "r"(da + i * 16), "l"(a + i * 8));
            asm volatile("cp.async.cg.shared.global [%0], [%1], 16;" :: "r"(db + i * 16), "l"(b + i * 8));
        }
        asm volatile("cp.async.commit_group;");
    };

    issue_stage(0, 0);

    const int arow = lane & 15;
    const int acol = (lane >> 4) * 8;

    for (int kt = 0; kt < nk; kt++) {
        int s = kt & 1;
        if (kt + 1 < nk) {
            issue_stage(kt + 1, s ^ 1);
            asm volatile("cp.async.wait_group 1;");
        } else {
            asm volatile("cp.async.wait_group 0;");
        }
        __syncthreads();

        __nv_bfloat16* As = sm + s * STAGE;
        __nv_bfloat16* Bs = As + BM * LDSS;
        uint32_t a_base = (uint32_t)__cvta_generic_to_shared(
            As + (wm * 64 + arow) * LDSS + acol);
        uint32_t b_base = (uint32_t)__cvta_generic_to_shared(
            Bs + (wn * 32 + arow) * LDSS + acol);

#pragma unroll
        for (int k16 = 0; k16 < 4; k16++) {
            uint32_t af[4][4];
#pragma unroll
            for (int mi = 0; mi < 4; mi++)
                LDSM_X4(af[mi], a_base + (mi * 16 * LDSS + k16 * 16) * 2);
            uint32_t bf[2][4];
#pragma unroll
            for (int nj = 0; nj < 2; nj++)
                LDSM_X4(bf[nj], b_base + (nj * 16 * LDSS + k16 * 16) * 2);
#pragma unroll
            for (int mi = 0; mi < 4; mi++) {
#pragma unroll
                for (int ng = 0; ng < 4; ng++) {
                    int nj = ng >> 1, hi = ng & 1;
                    MMA_BF16(acc[mi][ng], af[mi], bf[nj][hi], bf[nj][hi + 2]);
                }
            }
        }
        __syncthreads();
    }

    // Epilogue: add bias, convert to f16, route to g_x1h / g_x2h.
    const int row_t = lane >> 2;
    const int col_t = (lane & 3) * 2;
#pragma unroll
    for (int mi = 0; mi < 4; mi++) {
#pragma unroll
        for (int ng = 0; ng < 4; ng++) {
            int m = bm + wm * 64 + mi * 16 + row_t;
            int n = bn + wn * 32 + ng * 8 + col_t;
            float bi0 = g_bias[n], bi1 = g_bias[n + 1];
            __half* dst = (n < Aq) ? g_x1h : g_x2h;
            int nc = n & (Aq - 1);
            *(__half2*)(dst + (size_t)m * Aq + nc) =
                __floats2half2_rn(acc[mi][ng][0] + bi0, acc[mi][ng][1] + bi1);
            *(__half2*)(dst + (size_t)(m + 8) * Aq + nc) =
                __floats2half2_rn(acc[mi][ng][2] + bi0, acc[mi][ng][3] + bi1);
        }
    }
}

// ---------------- tanh + weighted reduction (v4: f16x2 tanh)
// 128 threads, tile 32i x 16j -> 1024 blocks (6.92/SM, ~1% wave imbalance),
// 8 blocks/SM. x1 f16 j-rows in smem (stride 520 halves: the 8 tj-threads'
// LDS.128 cover banks 0..31 exactly, conflict-free); x2 f16 via __ldg
// broadcast. tanh.approx.f16x2 = 2 elems/MUFU; f32 Wout + f32 accumulators.
#define TROWS 16
#define TITILE 32
#define HSTRIDE 520
#define SMEM_TANH (TROWS * HSTRIDE * 2 + Aq * 4)

__global__ __launch_bounds__(128, 8) void tanh_reduce(const float* __restrict__ Wout,
                                                      const float* __restrict__ bout,
                                                      float* __restrict__ out) {
    extern __shared__ char smc[];
    __half* s1 = (__half*)smc;                        // [16][520] x1 rows (j)
    float* sw = (float*)(smc + TROWS * HSTRIDE * 2);  // [512] Wout (f32)

    const int b  = blockIdx.z;
    const int it = blockIdx.y;
    const int jt = blockIdx.x;
    const int tid = threadIdx.x;
    const int j0base = jt * TROWS;
    const int i0base = it * TITILE;

    const __half* x1b = g_x1h + (size_t)b * Nq * Aq;
    const __half* x2b = g_x2h + (size_t)b * Nq * Aq;

    for (int idx = tid; idx < TROWS * (Aq / 8); idx += 128) {
        int row = idx >> 6;      // / 64
        int c8  = idx & 63;
        *(uint4*)(s1 + row * HSTRIDE + c8 * 8) =
            *(const uint4*)(x1b + (j0base + row) * Aq + c8 * 8);
    }
    if (tid < Aq / 4) ((float4*)sw)[tid] = ((const float4*)Wout)[tid];
    __syncthreads();

    const int ti = tid >> 3;   // 0..15
    const int tj = tid & 7;    // 0..7

    const __half* r1a = s1 + tj * HSTRIDE;
    const __half* r1b = s1 + (tj + 8) * HSTRIDE;

    const int i0g = i0base + ti;        // <= 111, always a valid output row
    const int i1g = i0g + 16;           // <= 127; row i1g+1 OOB only when ==127
    const uint4* r2a = (const uint4*)(x2b + (size_t)(i0g + 1) * Aq);
    const uint4* r2b = (const uint4*)(x2b +
        (size_t)((i1g < Nq - 1) ? (i1g + 1) : 0) * Aq);

    float acc00 = 0.f, acc01 = 0.f, acc10 = 0.f, acc11 = 0.f;

#pragma unroll 2
    for (int a8 = 0; a8 < Aq / 8; a8++) {
        uint4 pu = *(const uint4*)(r1a + a8 * 8);   // x1[j0], 8 halves
        uint4 qu = *(const uint4*)(r1b + a8 * 8);   // x1[j1]
        uint4 uu = __ldg(r2a + a8);                 // x2[i0+1]
        uint4 vu = __ldg(r2b + a8);                 // x2[i1+1]
        float4 w0 = ((const float4*)sw)[a8 * 2];
        float4 w1 = ((const float4*)sw)[a8 * 2 + 1];

        uint32_t pp[4] = {pu.x, pu.y, pu.z, pu.w};
        uint32_t qq[4] = {qu.x, qu.y, qu.z, qu.w};
        uint32_t us[4] = {uu.x, uu.y, uu.z, uu.w};
        uint32_t vv[4] = {vu.x, vu.y, vu.z, vu.w};
        float2 wk[4] = { make_float2(w0.x, w0.y), make_float2(w0.z, w0.w),
                         make_float2(w1.x, w1.y), make_float2(w1.z, w1.w) };

#pragma unroll
        for (int k = 0; k < 4; k++) {
            float2 f;
            f = h2_to_f2(htanh2(hadd2u(us[k], pp[k])));
            acc00 = fmaf(f.x, wk[k].x, acc00);
            acc00 = fmaf(f.y, wk[k].y, acc00);

            f = h2_to_f2(htanh2(hadd2u(us[k], qq[k])));
            acc01 = fmaf(f.x, wk[k].x, acc01);
            acc01 = fmaf(f.y, wk[k].y, acc01);

            f = h2_to_f2(htanh2(hadd2u(vv[k], pp[k])));
            acc10 = fmaf(f.x, wk[k].x, acc10);
            acc10 = fmaf(f.y, wk[k].y, acc10);

            f = h2_to_f2(htanh2(hadd2u(vv[k], qq[k])));
            acc11 = fmaf(f.x, wk[k].x, acc11);
            acc11 = fmaf(f.y, wk[k].y, acc11);
        }
    }

    const float bo = bout[0];
    const int j0g = j0base + tj, j1g = j0g + 8;
    float* ob = out + (size_t)b * (Nq - 1) * Nq;

    ob[i0g * Nq + j0g] = acc00 + bo;
    ob[i0g * Nq + j1g] = acc01 + bo;
    if (i1g < Nq - 1) {
        ob[i1g * Nq + j0g] = acc10 + bo;
        ob[i1g * Nq + j1g] = acc11 + bo;
    }
}

extern "C" void kernel_launch(void* const* d_in, const int* in_sizes, int n_in,
                              void* d_out, int out_size) {
    const float* x    = (const float*)d_in[0];
    const float* W1   = (const float*)d_in[1];
    const float* b1   = (const float*)d_in[2];
    const float* W2   = (const float*)d_in[3];
    const float* b2   = (const float*)d_in[4];
    const float* Wout = (const float*)d_in[5];
    const float* bout = (const float*)d_in[6];
    float* out = (float*)d_out;

    cudaFuncSetAttribute(tanh_reduce, cudaFuncAttributeMaxDynamicSharedMemorySize,
                         SMEM_TANH);
    cudaFuncSetAttribute(gemm_bf16, cudaFuncAttributeMaxDynamicSharedMemorySize,
                         SMEMG);

    split_x<<<(Mq * (Dq / 4) + 255) / 256, 256>>>(x);
    split_w<<<(NN * (Dq / 4) + 255) / 256, 256>>>(W1, W2, b1, b2);

    dim3 ggrid(NN / BN, Mq / BM);   // (8, 32)
    gemm_bf16<<<ggrid, 256, SMEMG>>>();

    dim3 tgrid(Nq / TROWS, Nq / TITILE, Bq);  // (8, 4, 32) = 1024 blocks
    tanh_reduce<<<tgrid, 128, SMEM_TANH>>>(Wout, bout, out);
}

// round 14
// speedup vs baseline: 1.6974x; 1.0245x over previous
#include <cuda_runtime.h>
#include <cuda_bf16.h>
#include <cuda_fp16.h>
#include <cstdint>

// Problem: B=32, N=128, D=512, A=512
//   x1 = x @ W1^T + b1   (B*N, A)
//   x2 = x @ W2^T + b2
//   out[b,i,j] = sum_a Wout[a]*tanh(x1[b,j,a] + x2[b,i+1,a]) + bout[0]
// GEMM via bf16 3-split tensor cores; x1/x2 stored as f16; tanh via
// tanh.approx.f16x2 (2 elems per MUFU op), f32 Wout + f32 accumulation.
// v5: software-pipelined (depth-3) LDG prefetch of x2 rows in tanh kernel.

#define Bq 32
#define Nq 128
#define Dq 512
#define Aq 512
#define Mq (Bq*Nq)     // 4096
#define KK 1536        // 3*512 split-K
#define NN 1024        // two weight matrices stacked

__device__ __half g_x1h[Mq*Aq];
__device__ __half g_x2h[Mq*Aq];
__device__ __nv_bfloat16 g_A[(size_t)Mq*KK];   // x split   [4096][1536]
__device__ __nv_bfloat16 g_B[(size_t)NN*KK];   // W split   [1024][1536]
__device__ float g_bias[NN];

__device__ __forceinline__ uint32_t htanh2(uint32_t x) {
    uint32_t y;
    asm("tanh.approx.f16x2 %0, %1;" : "=r"(y) : "r"(x));
    return y;
}

__device__ __forceinline__ uint32_t hadd2u(uint32_t a, uint32_t b) {
    uint32_t y;
    asm("add.f16x2 %0, %1, %2;" : "=r"(y) : "r"(a), "r"(b));
    return y;
}

__device__ __forceinline__ float2 h2_to_f2(uint32_t h) {
    __half2 hh = *(const __half2*)&h;
    return __half22float2(hh);
}

__device__ __forceinline__ uint32_t pack_bf2(__nv_bfloat16 a, __nv_bfloat16 b) {
    return (uint32_t)__bfloat16_as_ushort(a) | ((uint32_t)__bfloat16_as_ushort(b) << 16);
}

// ---------------- fused split kernel (fp32 -> bf16 hi/lo, 3-way K layout)
#define NX (Mq * (Dq / 4))   // 524288 x-chunks
#define NW (NN * (Dq / 4))   // 131072 w-chunks

__global__ __launch_bounds__(256) void split_xw(const float* __restrict__ x,
                                                const float* __restrict__ W1,
                                                const float* __restrict__ W2,
                                                const float* __restrict__ b1,
                                                const float* __restrict__ b2) {
    int idx = blockIdx.x * 256 + threadIdx.x;
    if (idx < NX) {
        int m = idx >> 7;          // / 128
        int k4 = idx & 127;
        float4 v = ((const float4*)x)[idx];
        float vv[4] = {v.x, v.y, v.z, v.w};
        __nv_bfloat16 h[4], l[4];
#pragma unroll
        for (int i = 0; i < 4; i++) {
            h[i] = __float2bfloat16(vv[i]);
            l[i] = __float2bfloat16(vv[i] - __bfloat162float(h[i]));
        }
        uint2 hu, lu;
        hu.x = pack_bf2(h[0], h[1]); hu.y = pack_bf2(h[2], h[3]);
        lu.x = pack_bf2(l[0], l[1]); lu.y = pack_bf2(l[2], l[3]);
        __nv_bfloat16* dst = g_A + (size_t)m * KK + k4 * 4;
        *(uint2*)(dst)        = hu;   // k [0,512)    : hi
        *(uint2*)(dst + 512)  = lu;   // k [512,1024) : lo
        *(uint2*)(dst + 1024) = hu;   // k [1024,1536): hi
    } else {
        int j = idx - NX;
        if (j < NN) g_bias[j] = (j < Aq) ? b1[j] : b2[j - Aq];
        if (j >= NW) return;
        int n = j >> 7;
        int k4 = j & 127;
        const float* src = (n < Aq) ? (W1 + (size_t)n * Dq)
                                    : (W2 + (size_t)(n - Aq) * Dq);
        float4 v = ((const float4*)src)[k4];
        float vv[4] = {v.x, v.y, v.z, v.w};
        __nv_bfloat16 h[4], l[4];
#pragma unroll
        for (int i = 0; i < 4; i++) {
            h[i] = __float2bfloat16(vv[i]);
            l[i] = __float2bfloat16(vv[i] - __bfloat162float(h[i]));
        }
        uint2 hu, lu;
        hu.x = pack_bf2(h[0], h[1]); hu.y = pack_bf2(h[2], h[3]);
        lu.x = pack_bf2(l[0], l[1]); lu.y = pack_bf2(l[2], l[3]);
        __nv_bfloat16* dst = g_B + (size_t)n * KK + k4 * 4;
        *(uint2*)(dst)        = hu;   // hi
        *(uint2*)(dst + 512)  = hu;   // hi (pairs with A lo)
        *(uint2*)(dst + 1024) = lu;   // lo (pairs with A hi)
    }
}

// ---------------- bf16 tensor-core GEMM: C[m,n] = sum_k A'[m,k]*B'[n,k] + bias[n]
#define BM 128
#define BN 128
#define BKg 64
#define LDSS 72                    // padded smem row stride (bf16 elems)
#define STAGE ((BM + BN) * LDSS)   // elems per stage
#define SMEMG (2 * STAGE * 2)      // bytes (2 stages)

#define LDSM_X4(r, addr) \
    asm volatile("ldmatrix.sync.aligned.m8n8.x4.shared.b16 {%0,%1,%2,%3}, [%4];" \
                 : "=r"((r)[0]), "=r"((r)[1]), "=r"((r)[2]), "=r"((r)[3]) : "r"(addr))

#define MMA_BF16(d, a, b0, b1) \
    asm volatile("mma.sync.aligned.m16n8k16.row.col.f32.bf16.bf16.f32 " \
                 "{%0,%1,%2,%3}, {%4,%5,%6,%7}, {%8,%9}, {%0,%1,%2,%3};" \
                 : "+f"((d)[0]), "+f"((d)[1]), "+f"((d)[2]), "+f"((d)[3]) \
                 : "r"((a)[0]), "r"((a)[1]), "r"((a)[2]), "r"((a)[3]), "r"(b0), "r"(b1))

__global__ __launch_bounds__(256, 2) void gemm_bf16() {
    extern __shared__ __nv_bfloat16 sm[];
    const int tid = threadIdx.x;
    const int warp = tid >> 5, lane = tid & 31;
    const int wm = warp & 1;
    const int wn = warp >> 1;
    const int bm = blockIdx.y * BM;
    const int bn = blockIdx.x * BN;

    float acc[4][4][4];
#pragma unroll
    for (int i = 0; i < 4; i++)
#pragma unroll
        for (int j = 0; j < 4; j++)
#pragma unroll
            for (int r = 0; r < 4; r++) acc[i][j][r] = 0.f;

    const __nv_bfloat16* Ag = g_A + (size_t)bm * KK;
    const __nv_bfloat16* Bg = g_B + (size_t)bn * KK;

    const int lrow = tid >> 1;
    const int lchunk = (tid & 1) * 4;
    const int nk = KK / BKg;                // 24

    auto issue_stage = [&](int kt, int s) {
        __nv_bfloat16* As = sm + s * STAGE;
        __nv_bfloat16* Bs = As + BM * LDSS;
        int k0 = kt * BKg;
        const __nv_bfloat16* a = Ag + (size_t)lrow * KK + k0 + lchunk * 8;
        const __nv_bfloat16* b = Bg + (size_t)lrow * KK + k0 + lchunk * 8;
        uint32_t da = (uint32_t)__cvta_generic_to_shared(As + lrow * LDSS + lchunk * 8);
        uint32_t db = (uint32_t)__cvta_generic_to_shared(Bs + lrow * LDSS + lchunk * 8);
#pragma unroll
        for (int i = 0; i < 4; i++) {
            asm volatile("cp.async.cg.shared.global [%0], [%1], 16;" :: "r"(da + i * 16), "l"(a + i * 8));
            asm volatile("cp.async.cg.shared.global [%0], [%1], 16;" :: "r"(db + i * 16), "l"(b + i * 8));
        }
        asm volatile("cp.async.commit_group;");
    };

    issue_stage(0, 0);

    const int arow = lane & 15;
    const int acol = (lane >> 4) * 8;

    for (int kt = 0; kt < nk; kt++) {
        int s = kt & 1;
        if (kt + 1 < nk) {
            issue_stage(kt + 1, s ^ 1);
            asm volatile("cp.async.wait_group 1;");
        } else {
            asm volatile("cp.async.wait_group 0;");
        }
        __syncthreads();

        __nv_bfloat16* As = sm + s * STAGE;
        __nv_bfloat16* Bs = As + BM * LDSS;
        uint32_t a_base = (uint32_t)__cvta_generic_to_shared(
            As + (wm * 64 + arow) * LDSS + acol);
        uint32_t b_base = (uint32_t)__cvta_generic_to_shared(
            Bs + (wn * 32 + arow) * LDSS + acol);

#pragma unroll
        for (int k16 = 0; k16 < 4; k16++) {
            uint32_t af[4][4];
#pragma unroll
            for (int mi = 0; mi < 4; mi++)
                LDSM_X4(af[mi], a_base + (mi * 16 * LDSS + k16 * 16) * 2);
            uint32_t bf[2][4];
#pragma unroll
            for (int nj = 0; nj < 2; nj++)
                LDSM_X4(bf[nj], b_base + (nj * 16 * LDSS + k16 * 16) * 2);
#pragma unroll
            for (int mi = 0; mi < 4; mi++) {
#pragma unroll
                for (int ng = 0; ng < 4; ng++) {
                    int nj = ng >> 1, hi = ng & 1;
                    MMA_BF16(acc[mi][ng], af[mi], bf[nj][hi], bf[nj][hi + 2]);
                }
            }
        }
        __syncthreads();
    }

    // Epilogue: add bias, convert to f16, route to g_x1h / g_x2h.
    const int row_t = lane >> 2;
    const int col_t = (lane & 3) * 2;
#pragma unroll
    for (int mi = 0; mi < 4; mi++) {
#pragma unroll
        for (int ng = 0; ng < 4; ng++) {
            int m = bm + wm * 64 + mi * 16 + row_t;
            int n = bn + wn * 32 + ng * 8 + col_t;
            float bi0 = g_bias[n], bi1 = g_bias[n + 1];
            __half* dst = (n < Aq) ? g_x1h : g_x2h;
            int nc = n & (Aq - 1);
            *(__half2*)(dst + (size_t)m * Aq + nc) =
                __floats2half2_rn(acc[mi][ng][0] + bi0, acc[mi][ng][1] + bi1);
            *(__half2*)(dst + (size_t)(m + 8) * Aq + nc) =
                __floats2half2_rn(acc[mi][ng][2] + bi0, acc[mi][ng][3] + bi1);
        }
    }
}

// ---------------- tanh + weighted reduction (v5: f16x2 tanh + LDG pipeline)
// 128 threads, tile 32i x 16j -> 1024 blocks, 8 blocks/SM. x1 f16 j-rows in
// smem; x2 f16 rows via __ldg with explicit depth-3 register pipeline (issue
// the k+2 load before processing k) to cover L2-hit latency (~234 cyc).
// tanh.approx.f16x2 = 2 elems/MUFU; f32 Wout + f32 accumulators.
#define TROWS 16
#define TITILE 32
#define HSTRIDE 520
#define SMEM_TANH (TROWS * HSTRIDE * 2 + Aq * 4)
#define NIT (Aq / 8)   // 64

__global__ __launch_bounds__(128, 8) void tanh_reduce(const float* __restrict__ Wout,
                                                      const float* __restrict__ bout,
                                                      float* __restrict__ out) {
    extern __shared__ char smc[];
    __half* s1 = (__half*)smc;                        // [16][520] x1 rows (j)
    float* sw = (float*)(smc + TROWS * HSTRIDE * 2);  // [512] Wout (f32)

    const int b  = blockIdx.z;
    const int it = blockIdx.y;
    const int jt = blockIdx.x;
    const int tid = threadIdx.x;
    const int j0base = jt * TROWS;
    const int i0base = it * TITILE;

    const __half* x1b = g_x1h + (size_t)b * Nq * Aq;
    const __half* x2b = g_x2h + (size_t)b * Nq * Aq;

    for (int idx = tid; idx < TROWS * (Aq / 8); idx += 128) {
        int row = idx >> 6;      // / 64
        int c8  = idx & 63;
        *(uint4*)(s1 + row * HSTRIDE + c8 * 8) =
            *(const uint4*)(x1b + (j0base + row) * Aq + c8 * 8);
    }
    if (tid < Aq / 4) ((float4*)sw)[tid] = ((const float4*)Wout)[tid];
    __syncthreads();

    const int ti = tid >> 3;   // 0..15
    const int tj = tid & 7;    // 0..7

    const __half* r1a = s1 + tj * HSTRIDE;
    const __half* r1b = s1 + (tj + 8) * HSTRIDE;

    const int i0g = i0base + ti;        // <= 111, always a valid output row
    const int i1g = i0g + 16;           // <= 127; row i1g+1 OOB only when ==127
    const uint4* r2a = (const uint4*)(x2b + (size_t)(i0g + 1) * Aq);
    const uint4* r2b = (const uint4*)(x2b +
        (size_t)((i1g < Nq - 1) ? (i1g + 1) : 0) * Aq);

    float acc00 = 0.f, acc01 = 0.f, acc10 = 0.f, acc11 = 0.f;

    // depth-3 LDG pipeline for u,v
    uint4 u0 = __ldg(r2a + 0), v0 = __ldg(r2b + 0);
    uint4 u1 = __ldg(r2a + 1), v1 = __ldg(r2b + 1);

#pragma unroll 2
    for (int a8 = 0; a8 < NIT; a8++) {
        int pf = a8 + 2; pf = (pf < NIT) ? pf : (NIT - 1);
        uint4 un = __ldg(r2a + pf);
        uint4 vn = __ldg(r2b + pf);

        uint4 pu = *(const uint4*)(r1a + a8 * 8);   // x1[j0], 8 halves
        uint4 qu = *(const uint4*)(r1b + a8 * 8);   // x1[j1]
        float4 w0 = ((const float4*)sw)[a8 * 2];
        float4 w1 = ((const float4*)sw)[a8 * 2 + 1];

        uint32_t pp[4] = {pu.x, pu.y, pu.z, pu.w};
        uint32_t qq[4] = {qu.x, qu.y, qu.z, qu.w};
        uint32_t us[4] = {u0.x, u0.y, u0.z, u0.w};
        uint32_t vv[4] = {v0.x, v0.y, v0.z, v0.w};
        float2 wk[4] = { make_float2(w0.x, w0.y), make_float2(w0.z, w0.w),
                         make_float2(w1.x, w1.y), make_float2(w1.z, w1.w) };

#pragma unroll
        for (int k = 0; k < 4; k++) {
            float2 f;
            f = h2_to_f2(htanh2(hadd2u(us[k], pp[k])));
            acc00 = fmaf(f.x, wk[k].x, acc00);
            acc00 = fmaf(f.y, wk[k].y, acc00);

            f = h2_to_f2(htanh2(hadd2u(us[k], qq[k])));
            acc01 = fmaf(f.x, wk[k].x, acc01);
            acc01 = fmaf(f.y, wk[k].y, acc01);

            f = h2_to_f2(htanh2(hadd2u(vv[k], pp[k])));
            acc10 = fmaf(f.x, wk[k].x, acc10);
            acc10 = fmaf(f.y, wk[k].y, acc10);

            f = h2_to_f2(htanh2(hadd2u(vv[k], qq[k])));
            acc11 = fmaf(f.x, wk[k].x, acc11);
            acc11 = fmaf(f.y, wk[k].y, acc11);
        }

        u0 = u1; v0 = v1;
        u1 = un; v1 = vn;
    }

    const float bo = bout[0];
    const int j0g = j0base + tj, j1g = j0g + 8;
    float* ob = out + (size_t)b * (Nq - 1) * Nq;

    ob[i0g * Nq + j0g] = acc00 + bo;
    ob[i0g * Nq + j1g] = acc01 + bo;
    if (i1g < Nq - 1) {
        ob[i1g * Nq + j0g] = acc10 + bo;
        ob[i1g * Nq + j1g] = acc11 + bo;
    }
}

extern "C" void kernel_launch(void* const* d_in, const int* in_sizes, int n_in,
                              void* d_out, int out_size) {
    const float* x    = (const float*)d_in[0];
    const float* W1   = (const float*)d_in[1];
    const float* b1   = (const float*)d_in[2];
    const float* W2   = (const float*)d_in[3];
    const float* b2   = (const float*)d_in[4];
    const float* Wout = (const float*)d_in[5];
    const float* bout = (const float*)d_in[6];
    float* out = (float*)d_out;

    cudaFuncSetAttribute(tanh_reduce, cudaFuncAttributeMaxDynamicSharedMemorySize,
                         SMEM_TANH);
    cudaFuncSetAttribute(gemm_bf16, cudaFuncAttributeMaxDynamicSharedMemorySize,
                         SMEMG);

    split_xw<<<(NX + NW + 255) / 256, 256>>>(x, W1, W2, b1, b2);

    dim3 ggrid(NN / BN, Mq / BM);   // (8, 32)
    gemm_bf16<<<ggrid, 256, SMEMG>>>();

    dim3 tgrid(Nq / TROWS, Nq / TITILE, Bq);  // (8, 4, 32) = 1024 blocks
    tanh_reduce<<<tgrid, 128, SMEM_TANH>>>(Wout, bout, out);
}